// round 17
// baseline (speedup 1.0000x reference)
#include <cuda_runtime.h>
#include <cuda_bf16.h>
#include <math.h>
#include <stdint.h>

// Problem constants (fixed by the dataset)
#define BB 8
#define SS 4096
#define DD 1024
#define MTOT (BB * SS)   // 32768

#define NCH 32
#define CHS (SS / NCH)   // 128 steps per chunk == GEMM M-tile
#define NCD (BB * DD)    // 8192 chains

// ---------------------------------------------------------------------------
// Scratch (device globals; no allocation allowed). Zero-initialized at load.
// ---------------------------------------------------------------------------
__device__ float          g_y[(size_t)MTOT * DD];     // within-chunk zero-init scan
__device__ float          g_w2[DD * DD];              // W2 = Wf*Wu (fp32)
__device__ __nv_bfloat16  g_wuthi[DD * DD];           // Wu^T hi/lo
__device__ __nv_bfloat16  g_wutlo[DD * DD];
__device__ __nv_bfloat16  g_wfhi[DD * DD];
__device__ __nv_bfloat16  g_wflo[DD * DD];
__device__ __nv_bfloat16  g_w2hi[DD * DD];
__device__ __nv_bfloat16  g_w2lo[DD * DD];
__device__ float          g_c[DD];                    // c = Wf*bu
__device__ float          g_zero[DD];                 // stays zero (never written)
__device__ float          g_P[BB * SS];               // within-chunk prefix products
__device__ float          g_Be[NCH * NCD];            // chunk-end scan values
__device__ float          g_cin[NCH * NCD];           // chunk carry-ins

// ---------------------------------------------------------------------------
// PTX helpers (base-target only; tcgen05 needs the '.a' target the harness
// nvcc does not emit)
// ---------------------------------------------------------------------------
__device__ __forceinline__ uint32_t smem_u32(const void* p) {
    uint32_t a;
    asm("{ .reg .u64 t; cvta.to.shared.u64 t, %1; cvt.u32.u64 %0, t; }" : "=r"(a) : "l"(p));
    return a;
}
__device__ __forceinline__ void cp16(uint32_t dst, const void* src) {
    asm volatile("cp.async.cg.shared.global [%0], [%1], 16;" :: "r"(dst), "l"(src));
}
__device__ __forceinline__ void cp_commit() {
    asm volatile("cp.async.commit_group;" ::: "memory");
}
template<int N>
__device__ __forceinline__ void cp_wait() {
    asm volatile("cp.async.wait_group %0;" :: "n"(N) : "memory");
}
__device__ __forceinline__ void ldm_x4(uint32_t* r, uint32_t addr) {
    asm volatile("ldmatrix.sync.aligned.m8n8.x4.shared.b16 {%0,%1,%2,%3}, [%4];"
                 : "=r"(r[0]), "=r"(r[1]), "=r"(r[2]), "=r"(r[3]) : "r"(addr));
}
__device__ __forceinline__ void mma16816(float* d, const uint32_t* a, const uint32_t* b) {
    asm volatile(
        "mma.sync.aligned.m16n8k16.row.col.f32.bf16.bf16.f32 "
        "{%0,%1,%2,%3}, {%4,%5,%6,%7}, {%8,%9}, {%0,%1,%2,%3};"
        : "+f"(d[0]), "+f"(d[1]), "+f"(d[2]), "+f"(d[3])
        : "r"(a[0]), "r"(a[1]), "r"(a[2]), "r"(a[3]), "r"(b[0]), "r"(b[1]));
}
__device__ __forceinline__ uint32_t pack_bf16x2(float a, float b) {
    __nv_bfloat162 h(__float2bfloat16_rn(a), __float2bfloat16_rn(b));
    return *reinterpret_cast<uint32_t*>(&h);
}
__device__ __forceinline__ float get_decay(const float* decay_p) {
    return 1.0f / (1.0f + expf(-decay_p[0]));
}

#define BN 128
#define BKK 32
#define ASTR 40                       // 32 + 8 pad bf16 -> 80B rows, conflict-free
#define TILE80 (128 * 80)             // 10240 B: one padded bf16 tile (128 rows)
#define NKB (DD / BKK)                // 32

// ---------------------------------------------------------------------------
// Big fused GEMM + chunk-scan epilogue, single-barrier pipelined mainloop.
//   y = x*W2^T + c  (x split to hi/lo bf16 in-smem, owner-computes: each
//   thread converts exactly the chunks it cp.async'd -> no barrier needed
//   between load and convert), then within-chunk zero-init scan of m*y.
// CTA tile 128x128, 8 warps (4x2), warp tile 32x64.
// smem: raw[2]*16KB + Acvt(hi+lo)[2]*20KB + B(hi+lo)[2]*20KB = 112KB, 2 CTA/SM.
// ---------------------------------------------------------------------------
#define RAW_B 16384
#define OFF_RAW 0
#define ACV_STAGE (2 * TILE80)                // 20480 (hi + lo)
#define OFF_ACV (2 * RAW_B)                   // 32768
#define OFF_B   (OFF_ACV + 2 * ACV_STAGE)     // 73728
#define FUSED_SMEM (OFF_B + 2 * 2 * TILE80)   // 114688
#define YSTR 132                              // padded fp32 row stride (epilogue)

__global__ __launch_bounds__(256, 2)
void gemm_xf32(const float* __restrict__ X,
               const __nv_bfloat16* __restrict__ Bhi,
               const __nv_bfloat16* __restrict__ Blo,
               const float* __restrict__ bias,
               const float* __restrict__ mask,
               const float* __restrict__ decay_p,
               float* __restrict__ Y,
               float* __restrict__ Be)
{
    extern __shared__ __align__(16) char smem[];
    const uint32_t sb = smem_u32(smem);

    const int tid  = threadIdx.x;
    const int wid  = tid >> 5;
    const int lane = tid & 31;
    const int wm   = wid & 3;    // warp row (M)
    const int wn   = wid >> 2;   // warp col (N)
    const int bx   = blockIdx.x; // N tile
    const int by   = blockIdx.y; // M tile == (b, chunk)

    // B loader
    const int r0  = tid >> 2;
    const int c16 = tid & 3;
    const __nv_bfloat16* Bh0 = Bhi + (size_t)(bx * BN + r0) * DD + c16 * 8;
    const __nv_bfloat16* Bl0 = Blo + (size_t)(bx * BN + r0) * DD + c16 * 8;
    const uint32_t dstb = (uint32_t)(r0 * 80 + c16 * 16);

    // ldmatrix addressing
    const int a_row = (lane & 7) + ((lane >> 3) & 1) * 8;
    const int a_col = (lane >> 4) * 8;
    const int b_row = (lane & 7) + (lane >> 4) * 8;
    const int b_col = ((lane >> 3) & 1) * 8;

    float acc[2][8][4];
    #pragma unroll
    for (int i = 0; i < 2; i++)
        #pragma unroll
        for (int j = 0; j < 8; j++)
            #pragma unroll
            for (int q = 0; q < 4; q++)
                acc[i][j][q] = 0.0f;

    // owner-computes: thread owns raw chunks u = tid + j*256 (row u>>3, 16B col u&7)
    auto issue_raw = [&](int kb, int st) {
        const int ko = kb * BKK;
        const uint32_t rawst = sb + OFF_RAW + st * RAW_B;
        #pragma unroll
        for (int j = 0; j < 4; j++) {
            const int u = tid + j * 256;
            const int row = u >> 3;
            const int cc  = u & 7;
            cp16(rawst + row * 128 + cc * 16,
                 X + (size_t)(by * 128 + row) * DD + ko + cc * 4);
        }
        cp_commit();
    };
    auto issue_B = [&](int kb, int st) {
        const int ko = kb * BKK;
        const uint32_t bst = sb + OFF_B + st * (2 * TILE80);
        #pragma unroll
        for (int j = 0; j < 2; j++) {
            const size_t ro = (size_t)j * 64 * DD;
            const uint32_t so = (uint32_t)(j * 64 * 80);
            cp16(bst + dstb + so, Bh0 + ro + ko);
            cp16(bst + TILE80 + dstb + so, Bl0 + ro + ko);
        }
        cp_commit();
    };
    // convert OWN chunks: raw[st] -> Acvt[st] hi/lo (no barrier needed)
    auto convert = [&](int st) {
        const uint32_t rawst = sb + OFF_RAW + st * RAW_B;
        const uint32_t acvst = sb + OFF_ACV + st * ACV_STAGE;
        #pragma unroll
        for (int j = 0; j < 4; j++) {
            const int u = tid + j * 256;
            const int row = u >> 3;
            const int cc  = u & 7;
            float4 v;
            asm volatile("ld.shared.v4.f32 {%0,%1,%2,%3}, [%4];"
                         : "=f"(v.x), "=f"(v.y), "=f"(v.z), "=f"(v.w)
                         : "r"(rawst + row * 128 + cc * 16));
            const uint32_t h0 = pack_bf16x2(v.x, v.y);
            const uint32_t h1 = pack_bf16x2(v.z, v.w);
            const float lx = v.x - __bfloat162float(__float2bfloat16_rn(v.x));
            const float ly = v.y - __bfloat162float(__float2bfloat16_rn(v.y));
            const float lz = v.z - __bfloat162float(__float2bfloat16_rn(v.z));
            const float lw = v.w - __bfloat162float(__float2bfloat16_rn(v.w));
            const uint32_t l0 = pack_bf16x2(lx, ly);
            const uint32_t l1 = pack_bf16x2(lz, lw);
            const uint32_t da = acvst + row * 80 + cc * 8;
            asm volatile("st.shared.v2.b32 [%0], {%1,%2};"
                         :: "r"(da), "r"(h0), "r"(h1) : "memory");
            asm volatile("st.shared.v2.b32 [%0], {%1,%2};"
                         :: "r"(da + TILE80), "r"(l0), "r"(l1) : "memory");
        }
    };

    // ---- prologue ----
    issue_raw(0, 0);            // group: raw0
    cp_wait<0>();
    convert(0);                 // own data -> Acvt0
    issue_B(0, 0);              // group: B0

    // ---- mainloop: ONE barrier per k-block ----
    for (int kb = 0; kb < NKB; kb++) {
        const int st = kb & 1;
        cp_wait<0>();           // B(kb) landed (own copies)
        __syncthreads();        // B(kb) + Acvt(kb) visible block-wide
        if (kb + 1 < NKB) {
            issue_raw(kb + 1, st ^ 1);   // group: raw(kb+1)
            issue_B(kb + 1, st ^ 1);     // group: B(kb+1)
        }

        const uint32_t stgA = sb + OFF_ACV + st * ACV_STAGE;
        const uint32_t stgB = sb + OFF_B + st * (2 * TILE80);
        #pragma unroll
        for (int ks = 0; ks < 2; ks++) {
            uint32_t aH[2][4], aL[2][4];
            #pragma unroll
            for (int mt = 0; mt < 2; mt++) {
                const uint32_t ra =
                    (uint32_t)(((wm * 32 + mt * 16 + a_row) * ASTR + ks * 16 + a_col) * 2);
                ldm_x4(aH[mt], stgA + ra);
                ldm_x4(aL[mt], stgA + TILE80 + ra);
            }
            #pragma unroll
            for (int g = 0; g < 4; g++) {
                const uint32_t rb =
                    (uint32_t)(((wn * 64 + g * 16 + b_row) * ASTR + ks * 16 + b_col) * 2);
                uint32_t bH[4], bL[4];
                ldm_x4(bH, stgB + rb);
                ldm_x4(bL, stgB + TILE80 + rb);
                #pragma unroll
                for (int mt = 0; mt < 2; mt++) {
                    mma16816(acc[mt][2 * g + 0], aH[mt], bH);
                    mma16816(acc[mt][2 * g + 1], aH[mt], bH + 2);
                    mma16816(acc[mt][2 * g + 0], aH[mt], bL);
                    mma16816(acc[mt][2 * g + 1], aH[mt], bL + 2);
                    mma16816(acc[mt][2 * g + 0], aL[mt], bH);
                    mma16816(acc[mt][2 * g + 1], aL[mt], bH + 2);
                }
            }
        }

        if (kb + 1 < NKB) {
            cp_wait<1>();        // raw(kb+1) done (B(kb+1) may be in flight)
            convert(st ^ 1);     // own data -> Acvt(kb+1); read after next sync
        }
    }

    // ---- epilogue: stage y(+bias) to smem, chunk-scan, write scan + Be ----
    __syncthreads();   // all smem reads of the mainloop done; reuse as fp32 tile
    {
        const int rb0 = wm * 32 + (lane >> 2);
        const int cb  = wn * 64 + (lane & 3) * 2;
        #pragma unroll
        for (int mt = 0; mt < 2; mt++) {
            #pragma unroll
            for (int nt = 0; nt < 8; nt++) {
                const int c = cb + nt * 8;
                const float2 bv = *(const float2*)(bias + bx * BN + c);
                float* p0 = (float*)(smem + ((rb0 + mt * 16) * YSTR + c) * 4);
                float* p1 = (float*)(smem + ((rb0 + mt * 16 + 8) * YSTR + c) * 4);
                p0[0] = acc[mt][nt][0] + bv.x;
                p0[1] = acc[mt][nt][1] + bv.y;
                p1[0] = acc[mt][nt][2] + bv.x;
                p1[1] = acc[mt][nt][3] + bv.y;
            }
        }
    }
    __syncthreads();

    const int bb = by >> 5;          // batch
    const int ch = by & 31;          // chunk
    if (tid < 128) {
        const float decay = get_decay(decay_p);
        const float* mrow = mask + (size_t)bb * SS + ch * CHS;
        float* col = (float*)(smem) + tid;
        float val = 0.0f;
        for (int s = 0; s < CHS; s += 8) {
            float mv[8], yv[8];
            #pragma unroll
            for (int i = 0; i < 8; i++) {
                mv[i] = mrow[s + i];
                yv[i] = col[(s + i) * YSTR];
            }
            #pragma unroll
            for (int i = 0; i < 8; i++) {
                const float a = mv[i] * decay + (1.0f - mv[i]);
                val = fmaf(a, val, mv[i] * yv[i]);
                col[(s + i) * YSTR] = val;
            }
        }
        Be[ch * NCD + bb * DD + bx * BN + tid] = val;
    }
    __syncthreads();

    // coalesced write of the scanned tile to Y
    #pragma unroll
    for (int j = 0; j < 16; j++) {
        const int u  = tid + j * 256;
        const int rw = u >> 5;
        const int c4 = (u & 31) * 4;
        const float4 v = *(const float4*)(smem + (rw * YSTR + c4) * 4);
        *(float4*)(Y + (size_t)(by * 128 + rw) * DD + bx * BN + c4) = v;
    }
}

// ---------------------------------------------------------------------------
// Small split-bf16 GEMM (pre-split operands) for W2 = Wf*Wu. M tile 64.
// ---------------------------------------------------------------------------
#define SM1_STAGE (2 * 64 * 80 + 2 * TILE80)
#define SM1_SMEM  (2 * SM1_STAGE)

__global__ __launch_bounds__(256, 2)
void gemm_w2(const __nv_bfloat16* __restrict__ Ahi,
             const __nv_bfloat16* __restrict__ Alo,
             const __nv_bfloat16* __restrict__ Bhi,
             const __nv_bfloat16* __restrict__ Blo,
             const float* __restrict__ bias,
             float* __restrict__ C)
{
    constexpr int ATILE_B = 64 * 80;
    extern __shared__ __align__(16) char smem[];
    const uint32_t sb = smem_u32(smem);

    const int tid  = threadIdx.x;
    const int wid  = tid >> 5;
    const int lane = tid & 31;
    const int wm   = wid & 3;
    const int wn   = wid >> 2;
    const int bx   = blockIdx.x;
    const int by   = blockIdx.y;

    const int r0  = tid >> 2;    // 0..63
    const int c16 = tid & 3;
    const __nv_bfloat16* Ah0 = Ahi + (size_t)(by * 64 + r0) * DD + c16 * 8;
    const __nv_bfloat16* Al0 = Alo + (size_t)(by * 64 + r0) * DD + c16 * 8;
    const __nv_bfloat16* Bh0 = Bhi + (size_t)(bx * BN + r0) * DD + c16 * 8;
    const __nv_bfloat16* Bl0 = Blo + (size_t)(bx * BN + r0) * DD + c16 * 8;
    const uint32_t dsta = (uint32_t)(r0 * 80 + c16 * 16);

    const int a_row = (lane & 7) + ((lane >> 3) & 1) * 8;
    const int a_col = (lane >> 4) * 8;
    const int b_row = (lane & 7) + (lane >> 4) * 8;
    const int b_col = ((lane >> 3) & 1) * 8;

    float acc[8][4];
    #pragma unroll
    for (int j = 0; j < 8; j++)
        #pragma unroll
        for (int q = 0; q < 4; q++)
            acc[j][q] = 0.0f;

    auto issue = [&](int kb, int st) {
        const uint32_t stg = sb + st * SM1_STAGE;
        const int ko = kb * BKK;
        cp16(stg + dsta, Ah0 + ko);
        cp16(stg + ATILE_B + dsta, Al0 + ko);
        #pragma unroll
        for (int j = 0; j < 2; j++) {
            const size_t ro = (size_t)j * 64 * DD;
            const uint32_t so = (uint32_t)(j * 64 * 80);
            cp16(stg + 2 * ATILE_B + dsta + so, Bh0 + ro + ko);
            cp16(stg + 2 * ATILE_B + TILE80 + dsta + so, Bl0 + ro + ko);
        }
        cp_commit();
    };

    issue(0, 0);
    for (int kb = 0; kb < NKB; kb++) {
        const int st = kb & 1;
        cp_wait<0>();
        __syncthreads();
        if (kb + 1 < NKB) issue(kb + 1, st ^ 1);

        const uint32_t stg = sb + st * SM1_STAGE;
        #pragma unroll
        for (int ks = 0; ks < 2; ks++) {
            uint32_t aH[4], aL[4];
            const uint32_t ra = (uint32_t)(((wm * 16 + a_row) * ASTR + ks * 16 + a_col) * 2);
            ldm_x4(aH, stg + ra);
            ldm_x4(aL, stg + ATILE_B + ra);
            #pragma unroll
            for (int g = 0; g < 4; g++) {
                const uint32_t rb = (uint32_t)(((wn * 64 + g * 16 + b_row) * ASTR + ks * 16 + b_col) * 2);
                uint32_t bH[4], bL[4];
                ldm_x4(bH, stg + 2 * ATILE_B + rb);
                ldm_x4(bL, stg + 2 * ATILE_B + TILE80 + rb);
                mma16816(acc[2 * g + 0], aH, bH);
                mma16816(acc[2 * g + 1], aH, bH + 2);
                mma16816(acc[2 * g + 0], aH, bL);
                mma16816(acc[2 * g + 1], aH, bL + 2);
                mma16816(acc[2 * g + 0], aL, bH);
                mma16816(acc[2 * g + 1], aL, bH + 2);
            }
        }
    }

    const int crow = by * 64 + wm * 16 + (lane >> 2);
    const int ccol = bx * BN + wn * 64 + (lane & 3) * 2;
    #pragma unroll
    for (int nt = 0; nt < 8; nt++) {
        const int gn = ccol + nt * 8;
        const float2 bv = *(const float2*)(bias + gn);
        float2 o0, o1;
        o0.x = acc[nt][0] + bv.x;
        o0.y = acc[nt][1] + bv.y;
        o1.x = acc[nt][2] + bv.x;
        o1.y = acc[nt][3] + bv.y;
        *(float2*)(C + (size_t)crow * DD + gn)       = o0;
        *(float2*)(C + (size_t)(crow + 8) * DD + gn) = o1;
    }
}

// ---------------------------------------------------------------------------
// fp32 -> (hi, lo) bf16 split (plain)
// ---------------------------------------------------------------------------
__global__ void split_kernel(const float* __restrict__ in,
                             __nv_bfloat16* __restrict__ hi,
                             __nv_bfloat16* __restrict__ lo, int n4)
{
    for (int i = blockIdx.x * blockDim.x + threadIdx.x; i < n4; i += gridDim.x * blockDim.x) {
        const float4 v = ((const float4*)in)[i];
        __nv_bfloat16 hx = __float2bfloat16_rn(v.x);
        __nv_bfloat16 hy = __float2bfloat16_rn(v.y);
        __nv_bfloat16 hz = __float2bfloat16_rn(v.z);
        __nv_bfloat16 hw = __float2bfloat16_rn(v.w);
        __nv_bfloat162* h2 = (__nv_bfloat162*)hi;
        __nv_bfloat162* l2 = (__nv_bfloat162*)lo;
        h2[2 * i + 0] = __nv_bfloat162(hx, hy);
        h2[2 * i + 1] = __nv_bfloat162(hz, hw);
        l2[2 * i + 0] = __nv_bfloat162(__float2bfloat16_rn(v.x - __bfloat162float(hx)),
                                       __float2bfloat16_rn(v.y - __bfloat162float(hy)));
        l2[2 * i + 1] = __nv_bfloat162(__float2bfloat16_rn(v.z - __bfloat162float(hz)),
                                       __float2bfloat16_rn(v.w - __bfloat162float(hw)));
    }
}

// ---------------------------------------------------------------------------
// transposing split: Wu (fp32) -> Wu^T hi/lo (bf16), one pass
// ---------------------------------------------------------------------------
__global__ void split_t_kernel(const float* __restrict__ in,
                               __nv_bfloat16* __restrict__ hi,
                               __nv_bfloat16* __restrict__ lo)
{
    __shared__ float t[32][33];
    const int x  = blockIdx.x * 32 + threadIdx.x;
    const int y0 = blockIdx.y * 32 + threadIdx.y;
    #pragma unroll
    for (int j = 0; j < 4; j++)
        t[threadIdx.y + j * 8][threadIdx.x] = in[(size_t)(y0 + j * 8) * DD + x];
    __syncthreads();
    const int x2 = blockIdx.y * 32 + threadIdx.x;
    const int y2 = blockIdx.x * 32 + threadIdx.y;
    #pragma unroll
    for (int j = 0; j < 4; j++) {
        const float v = t[threadIdx.x][threadIdx.y + j * 8];
        const __nv_bfloat16 h = __float2bfloat16_rn(v);
        hi[(size_t)(y2 + j * 8) * DD + x2] = h;
        lo[(size_t)(y2 + j * 8) * DD + x2] = __float2bfloat16_rn(v - __bfloat162float(h));
    }
}

// ---------------------------------------------------------------------------
// c[e] = sum_d Wf[e,d] * bu[d]
// ---------------------------------------------------------------------------
__global__ void bias_proj(const float* __restrict__ Wf,
                          const float* __restrict__ bu,
                          float* __restrict__ c)
{
    __shared__ float red[8];
    const int e = blockIdx.x;
    float s = 0.0f;
    for (int d = threadIdx.x; d < DD; d += 256)
        s += Wf[(size_t)e * DD + d] * bu[d];
    #pragma unroll
    for (int o = 16; o > 0; o >>= 1)
        s += __shfl_down_sync(0xffffffffu, s, o);
    if ((threadIdx.x & 31) == 0) red[threadIdx.x >> 5] = s;
    __syncthreads();
    if (threadIdx.x == 0) {
        float t = 0.0f;
        #pragma unroll
        for (int w = 0; w < 8; w++) t += red[w];
        c[e] = t;
    }
}

// ---------------------------------------------------------------------------
// Parallel prefix products: 256 blocks (one per (b,ch)) x 128 threads.
// Thread t computes a_t, then log-step inclusive PRODUCT scan:
// shfl within warps + 4-warp smem combine.
// ---------------------------------------------------------------------------
__global__ void prefix_kernel(const float* __restrict__ mask,
                              const float* __restrict__ decay_p,
                              float* __restrict__ P)
{
    __shared__ float wtot[4];
    const int g  = blockIdx.x;          // 0..255
    const int b  = g >> 5;
    const int ch = g & 31;
    const int t    = threadIdx.x;       // 0..127
    const int lane = t & 31;
    const int w    = t >> 5;

    const float decay = get_decay(decay_p);
    const float m = mask[(size_t)b * SS + ch * CHS + t];
    float a = m * decay + (1.0f - m);

    // inclusive product scan within warp
    #pragma unroll
    for (int o = 1; o < 32; o <<= 1) {
        const float v = __shfl_up_sync(0xffffffffu, a, o);
        if (lane >= o) a *= v;
    }
    if (lane == 31) wtot[w] = a;
    __syncthreads();

    float mult = 1.0f;
    #pragma unroll
    for (int i = 0; i < 4; i++)
        if (i < w) mult *= wtot[i];

    P[(size_t)b * SS + ch * CHS + t] = a * mult;
}

// ---------------------------------------------------------------------------
// combine: chain chunk summaries per (b,d). A_ch = P at chunk end.
// ---------------------------------------------------------------------------
__global__ void scan_combine(const float* __restrict__ P,
                             const float* __restrict__ Be,
                             float* __restrict__ cin)
{
    const int g = blockIdx.x * blockDim.x + threadIdx.x;   // 0..8191 = b*DD+d
    const int b = g >> 10;
    float carry = 0.0f;
    #pragma unroll
    for (int ch = 0; ch < NCH; ch++) {
        cin[ch * NCD + g] = carry;
        const float A = P[(size_t)b * SS + ch * CHS + (CHS - 1)];
        carry = fmaf(A, carry, Be[ch * NCD + g]);
    }
}

// ---------------------------------------------------------------------------
// finish (fully parallel streaming): out = yscan + P_t * cin + bf
// ---------------------------------------------------------------------------
__global__ void scan_finish(const float* __restrict__ Y,
                            const float* __restrict__ P,
                            const float* __restrict__ cin,
                            const float* __restrict__ bf,
                            float* __restrict__ out)
{
    const int n4 = MTOT * DD / 4;
    for (int i = blockIdx.x * blockDim.x + threadIdx.x; i < n4; i += gridDim.x * blockDim.x) {
        const int m  = i >> 8;            // row (b*SS + s)
        const int d  = (i & 255) * 4;
        const int b  = m >> 12;
        const int s  = m & (SS - 1);
        const int ch = s >> 7;
        const float p = P[(size_t)b * SS + s];
        const float4 yv = *(const float4*)(Y + (size_t)m * DD + d);
        const float4 cv = *(const float4*)(cin + ch * NCD + b * DD + d);
        const float4 bv = *(const float4*)(bf + d);
        float4 o;
        o.x = fmaf(p, cv.x, yv.x) + bv.x;
        o.y = fmaf(p, cv.y, yv.y) + bv.y;
        o.z = fmaf(p, cv.z, yv.z) + bv.z;
        o.w = fmaf(p, cv.w, yv.w) + bv.w;
        *(float4*)(out + (size_t)m * DD + d) = o;
    }
}

// ---------------------------------------------------------------------------
// kernel_launch
// Inputs: 0:x (B,S,D)  1:mask (B,S)  2:Wu (D,D)  3:bu (D)
//         4:Wf (D,D)   5:bf (D)      6:decay_param (1)
//
// Math: out = scan(m*(x*Wu^T + bu))*Wf^T + bf == scan(m*(x*W2^T + c)) + bf
//       with W2 = Wf*Wu, c = Wf*bu. Chunked scan:
//       mem_t = scan0_t + P_t*cin (within-chunk scan in the GEMM epilogue).
// ---------------------------------------------------------------------------
extern "C" void kernel_launch(void* const* d_in, const int* in_sizes, int n_in,
                              void* d_out, int out_size)
{
    const float* x     = (const float*)d_in[0];
    const float* mask  = (const float*)d_in[1];
    const float* Wu    = (const float*)d_in[2];
    const float* bu    = (const float*)d_in[3];
    const float* Wf    = (const float*)d_in[4];
    const float* bf    = (const float*)d_in[5];
    const float* decay = (const float*)d_in[6];
    float* out = (float*)d_out;

    float *y, *w2, *cvec, *zero, *P, *Be, *cin;
    __nv_bfloat16 *wuthi, *wutlo, *wfhi, *wflo, *w2hi, *w2lo;
    cudaGetSymbolAddress((void**)&y,     g_y);
    cudaGetSymbolAddress((void**)&w2,    g_w2);
    cudaGetSymbolAddress((void**)&wuthi, g_wuthi);
    cudaGetSymbolAddress((void**)&wutlo, g_wutlo);
    cudaGetSymbolAddress((void**)&wfhi,  g_wfhi);
    cudaGetSymbolAddress((void**)&wflo,  g_wflo);
    cudaGetSymbolAddress((void**)&w2hi,  g_w2hi);
    cudaGetSymbolAddress((void**)&w2lo,  g_w2lo);
    cudaGetSymbolAddress((void**)&cvec,  g_c);
    cudaGetSymbolAddress((void**)&zero,  g_zero);
    cudaGetSymbolAddress((void**)&P,     g_P);
    cudaGetSymbolAddress((void**)&Be,    g_Be);
    cudaGetSymbolAddress((void**)&cin,   g_cin);

    cudaFuncSetAttribute(gemm_xf32, cudaFuncAttributeMaxDynamicSharedMemorySize, FUSED_SMEM);
    cudaFuncSetAttribute(gemm_w2,   cudaFuncAttributeMaxDynamicSharedMemorySize, SM1_SMEM);

    // --- weight prep + prefix products (small) ---
    split_t_kernel<<<dim3(32, 32), dim3(32, 8)>>>(Wu, wuthi, wutlo);   // Wu^T hi/lo
    split_kernel<<<128, 256>>>(Wf, wfhi, wflo, DD * DD / 4);
    bias_proj<<<DD, 256>>>(Wf, bu, cvec);                              // c = Wf*bu
    prefix_kernel<<<BB * NCH, CHS>>>(mask, decay, P);                  // parallel scan

    // W2 = Wf * Wu
    gemm_w2<<<dim3(DD / BN, 1024 / 64), 256, SM1_SMEM>>>(
        wfhi, wflo, wuthi, wutlo, zero, w2);
    split_kernel<<<128, 256>>>(w2, w2hi, w2lo, DD * DD / 4);

    // --- big path: y = x*W2^T + c, within-chunk scan fused in epilogue ---
    gemm_xf32<<<dim3(DD / BN, MTOT / 128), 256, FUSED_SMEM>>>(
        x, w2hi, w2lo, cvec, mask, decay, y, Be);

    // chunk combine + fully-parallel finish
    scan_combine<<<NCD / 256, 256>>>(P, Be, cin);
    scan_finish<<<4096, 256>>>(y, P, cin, bf, out);
}